// round 10
// baseline (speedup 1.0000x reference)
#include <cuda_runtime.h>
#include <cuda_fp16.h>
#include <cstdint>
#include <cstddef>

#define TSEQ 512
#define BATCH 128
#define HDIM 1024
#define NZ 4096
#define VOC 128
#define EDIM 256
#define NBLK 128

// ---------------- static device buffers ----------------
__device__ half  d_U16[(size_t)NZ * HDIM];            // U^T fp16 [n][k], 8 MB
__device__ float d_embW[VOC * NZ];                    // emb@W + b  [v][n], 2 MB
__device__ half  d_A16[2][BATCH * HDIM];              // ping-pong h (fp16)
__device__ float d_c[BATCH * HDIM];
__device__ float d_h[BATCH * HDIM];
__device__ float d_S[(size_t)BATCH * TSEQ * HDIM];    // fp32 states, 256 MB
__device__ unsigned g_cnt;                            // grid barrier state
__device__ unsigned g_gen;

// ---------------- PTX helpers ----------------
__device__ __forceinline__ unsigned smaddr(const void* p) {
    return (unsigned)__cvta_generic_to_shared(p);
}
__device__ __forceinline__ void cpa16(void* dst, const void* src) {
    asm volatile("cp.async.cg.shared.global [%0], [%1], 16;\n"
                 :: "r"(smaddr(dst)), "l"(src));
}
__device__ __forceinline__ void ldsm_x4(unsigned* r, const void* p) {
    unsigned a = smaddr(p);
    asm volatile("ldmatrix.sync.aligned.m8n8.x4.shared.b16 {%0,%1,%2,%3}, [%4];\n"
                 : "=r"(r[0]), "=r"(r[1]), "=r"(r[2]), "=r"(r[3]) : "r"(a));
}
__device__ __forceinline__ void ldsm_x2(unsigned* r, const void* p) {
    unsigned a = smaddr(p);
    asm volatile("ldmatrix.sync.aligned.m8n8.x2.shared.b16 {%0,%1}, [%2];\n"
                 : "=r"(r[0]), "=r"(r[1]) : "r"(a));
}
__device__ __forceinline__ void mma16816(float* d, const unsigned* a, const unsigned* b) {
    asm volatile("mma.sync.aligned.m16n8k16.row.col.f32.f16.f16.f32 "
                 "{%0,%1,%2,%3},{%4,%5,%6,%7},{%8,%9},{%0,%1,%2,%3};\n"
                 : "+f"(d[0]), "+f"(d[1]), "+f"(d[2]), "+f"(d[3])
                 : "r"(a[0]), "r"(a[1]), "r"(a[2]), "r"(a[3]),
                   "r"(b[0]), "r"(b[1]));
}
__device__ __forceinline__ float sigmoidf_acc(float x) {
    return 1.0f / (1.0f + expf(-x));
}

// ---------------- prep: embW = emb @ W + b   (128 x 4096, K=256) ----------------
__global__ void __launch_bounds__(256) prep_embW(const float* __restrict__ emb,
                                                 const float* __restrict__ W,
                                                 const float* __restrict__ bias) {
    __shared__ float Ws[EDIM][32];
    const int n0 = blockIdx.x * 32;
    for (int i = threadIdx.x; i < EDIM * 32; i += 256) {
        int e = i >> 5, c = i & 31;
        Ws[e][c] = W[(size_t)e * NZ + n0 + c];
    }
    __syncthreads();
    const int c = threadIdx.x & 31;
    for (int v = threadIdx.x >> 5; v < VOC; v += 8) {
        float a = bias[n0 + c];
        const float* er = emb + v * EDIM;
        #pragma unroll 8
        for (int e = 0; e < EDIM; e++) a += er[e] * Ws[e][c];
        d_embW[v * NZ + n0 + c] = a;
    }
}

// ---------------- prep: U fp32 [k][n] -> d_U16 fp16 [n][k] ----------------
__global__ void __launch_bounds__(256) prep_U(const float* __restrict__ U) {
    __shared__ float tile[32][33];
    const int n0 = blockIdx.x * 32;
    const int k0 = blockIdx.y * 32;
    const int tx = threadIdx.x & 31, ty = threadIdx.x >> 5;
    #pragma unroll
    for (int i = 0; i < 4; i++) {
        int r = ty + i * 8;
        tile[r][tx] = U[(size_t)(k0 + r) * NZ + n0 + tx];
    }
    __syncthreads();
    #pragma unroll
    for (int i = 0; i < 4; i++) {
        int r = ty + i * 8;
        d_U16[(size_t)(n0 + r) * HDIM + k0 + tx] = __float2half_rn(tile[tx][r]);
    }
}

__global__ void init_state() {
    int i = blockIdx.x * blockDim.x + threadIdx.x;
    if (i < BATCH * HDIM) {
        d_c[i] = 0.f;
        d_h[i] = 0.f;
        d_A16[0][i] = __float2half_rn(0.f);
    }
}

// ---------------- persistent LSTM ----------------
// Block bn owns h-cols [8bn,8bn+8) => z-cols {g*1024 + 8bn + j}.
// 16 warps = 4 M-groups (wm: 32 rows) x 4 K-slices (kw: 256 k).
// Each warp: full N=32, private 2-stage A ring, NO mainloop barriers.
// K-partials reduced via smem (reusing dead A stages), fused into epilogue.
#define KC 64
#define B_ROWH 1032                             // 1024 + 8 pad halfs
#define B_H    (32 * B_ROWH)                    // 33024 halfs = 66048 B
#define A_STG_H (32 * 72)                       // 2304 halfs = 4608 B per stage
#define SMEM_TOTAL ((B_H + 16 * 2 * A_STG_H) * 2)   // 66048 + 147456 = 213504 B

__global__ void __launch_bounds__(512) lstm_persist(const int* __restrict__ tokens) {
    extern __shared__ __align__(16) half smh[];
    half*  Bs   = smh;                                   // B[32][1032]
    float* part = reinterpret_cast<float*>(smh + B_H);   // [4][128][33] = 67584 B (A region)

    const int tid  = threadIdx.x;
    const int bn   = blockIdx.x;
    const int lane = tid & 31, wid = tid >> 5;
    const int wm   = wid & 3;      // M-group: rows [wm*32, wm*32+32)
    const int kw   = wid >> 2;     // K-slice: k in [kw*256, kw*256+256)

    half* Aw = smh + B_H + wid * (2 * A_STG_H);          // private 2-stage ring

    unsigned gen = 0;
    if (tid == 0) gen = *(volatile unsigned*)&g_gen;

    // ---- B preload ONCE: 32 cols x 1024 k ----
    #pragma unroll
    for (int w = 0; w < 8; w++) {
        int i = tid + w * 512;                 // 0..4095
        int ci = i >> 7, seg = i & 127;
        int gcol = (ci >> 3) * HDIM + bn * 8 + (ci & 7);
        cpa16(Bs + ci * B_ROWH + seg * 8, d_U16 + (size_t)gcol * HDIM + seg * 8);
    }
    asm volatile("cp.async.commit_group;\ncp.async.wait_group 0;\n");
    __syncthreads();

    const int aRowL = (lane & 7) + ((lane >> 3) & 1) * 8;
    const int aCol  = ((lane >> 4) & 1) * 8;
    const int bKsel = ((lane >> 3) & 1) * 8;

    for (int t = 0; t < TSEQ; t++) {
        const int rb = t & 1, wb = rb ^ 1;
        const half* __restrict__ Asrc = d_A16[rb];

        // warp-private A loader: 32 rows x 64 k = 256 x 16B, 8 cpa16/lane
        auto load_A = [&](int ch) {
            half* st = Aw + (ch & 1) * A_STG_H;
            const int k0 = kw * 256 + ch * KC;
            #pragma unroll
            for (int w = 0; w < 8; w++) {
                int i = lane + w * 32;                    // 0..255
                int row = i >> 3, seg = i & 7;
                cpa16(st + row * 72 + seg * 8,
                      Asrc + (size_t)(wm * 32 + row) * HDIM + k0 + seg * 8);
            }
            asm volatile("cp.async.commit_group;\n");
        };
        load_A(0); load_A(1);

        float acc[2][4][4];
        #pragma unroll
        for (int i = 0; i < 2; i++)
            #pragma unroll
            for (int j = 0; j < 4; j++)
                #pragma unroll
                for (int e = 0; e < 4; e++) acc[i][j][e] = 0.f;

        for (int ch = 0; ch < 4; ch++) {
            asm volatile("cp.async.wait_group 1;\n");     // chunk ch resident (private)

            const half* st = Aw + (ch & 1) * A_STG_H;
            const int kOffB = kw * 256 + ch * KC + bKsel;
            #pragma unroll
            for (int ks = 0; ks < 4; ks++) {
                unsigned af0[4], af1[4], bf[4][2];
                ldsm_x4(af0, st + (aRowL     ) * 72 + aCol + ks * 16);
                ldsm_x4(af1, st + (aRowL + 16) * 72 + aCol + ks * 16);
                #pragma unroll
                for (int nt = 0; nt < 4; nt++)
                    ldsm_x2(bf[nt], Bs + (nt * 8 + (lane & 7)) * B_ROWH
                                       + kOffB + ks * 16);
                #pragma unroll
                for (int nt = 0; nt < 4; nt++) {
                    mma16816(acc[0][nt], af0, bf[nt]);
                    mma16816(acc[1][nt], af1, bf[nt]);
                }
            }

            if (ch < 2) load_A(ch + 2);                   // slot freed: MMAs issued
            else asm volatile("cp.async.commit_group;\n");
        }
        asm volatile("cp.async.wait_group 0;\n");
        __syncthreads();                                   // all warps done with A/B reads

        // ---- store K-partials to smem (overlaps dead A stages) ----
        #pragma unroll
        for (int mt = 0; mt < 2; mt++)
            #pragma unroll
            for (int nt = 0; nt < 4; nt++)
                #pragma unroll
                for (int e = 0; e < 4; e++) {
                    int r = wm * 32 + mt * 16 + (lane >> 2) + (e >> 1) * 8;
                    int c = nt * 8 + (lane & 3) * 2 + (e & 1);
                    part[((kw << 7) + r) * 33 + c] = acc[mt][nt][e];
                }
        __syncthreads();

        // ---- reduce partials + gate + state update: 2 elements/thread ----
        #pragma unroll
        for (int rep = 0; rep < 2; rep++) {
            const int e   = tid + rep * 512;
            const int bb  = e >> 3, j = e & 7;
            const int col = bn * 8 + j;
            const int tok = tokens[bb * TSEQ + t];
            const float* ew = d_embW + (size_t)tok * NZ + col;
            const float* pr = part + bb * 33;

            float zi = pr[j]      + pr[128*33 + j]      + pr[256*33 + j]      + pr[384*33 + j]      + ew[0];
            float zf = pr[8 + j]  + pr[128*33 + 8 + j]  + pr[256*33 + 8 + j]  + pr[384*33 + 8 + j]  + ew[HDIM];
            float zg = pr[16 + j] + pr[128*33 + 16 + j] + pr[256*33 + 16 + j] + pr[384*33 + 16 + j] + ew[2 * HDIM];
            float zo = pr[24 + j] + pr[128*33 + 24 + j] + pr[256*33 + 24 + j] + pr[384*33 + 24 + j] + ew[3 * HDIM];

            float ig = sigmoidf_acc(zi);
            float fg = sigmoidf_acc(zf);
            float gg = tanhf(zg);
            float og = sigmoidf_acc(zo);

            const int si = bb * HDIM + col;
            float cp = d_c[si];
            float cn = fg * cp + ig * gg;
            float hn = og * tanhf(cn);

            bool msk = (tok != 0);
            float ho = msk ? hn : d_h[si];
            float co = msk ? cn : cp;

            d_c[si] = co;
            d_h[si] = ho;
            d_S[((size_t)bb * TSEQ + t) * HDIM + col] = ho;
            d_A16[wb][si] = __float2half_rn(ho);
        }

        // ---- grid barrier: h(t) published to all blocks ----
        __threadfence();
        __syncthreads();
        if (tid == 0) {
            unsigned arr = atomicAdd(&g_cnt, 1);
            if (arr == NBLK - 1) {
                g_cnt = 0;
                __threadfence();
                atomicExch(&g_gen, gen + 1);
            } else {
                while (*(volatile unsigned*)&g_gen != gen + 1) { }
            }
            __threadfence();
        }
        __syncthreads();
        gen++;
    }
}

// ---------------- decode + softmax ----------------
__global__ void __launch_bounds__(256) decode_kernel(const float* __restrict__ Wd,
                                                     const float* __restrict__ bd,
                                                     float* __restrict__ out) {
    __shared__ float s[64][33];
    __shared__ float w[32][128];
    const int row0 = blockIdx.x * 64;
    const int tid  = threadIdx.x;
    const int r    = tid >> 2;
    const int q    = tid & 3;

    float acc[32];
    #pragma unroll
    for (int i = 0; i < 32; i++) acc[i] = 0.f;

    for (int kt = 0; kt < 32; kt++) {
        for (int i = tid; i < 64 * 32; i += 256) {
            int rr = i >> 5, kk = i & 31;
            s[rr][kk] = d_S[(size_t)(row0 + rr) * HDIM + kt * 32 + kk];
        }
        for (int i = tid; i < 32 * 128; i += 256) {
            int kk = i >> 7, cc = i & 127;
            w[kk][cc] = Wd[(size_t)(kt * 32 + kk) * VOC + cc];
        }
        __syncthreads();

        #pragma unroll 4
        for (int kk = 0; kk < 32; kk++) {
            float sv = s[r][kk];
            const float4* wrow = reinterpret_cast<const float4*>(&w[kk][q * 32]);
            #pragma unroll
            for (int c4 = 0; c4 < 8; c4++) {
                float4 wv = wrow[c4];
                acc[c4 * 4 + 0] += sv * wv.x;
                acc[c4 * 4 + 1] += sv * wv.y;
                acc[c4 * 4 + 2] += sv * wv.z;
                acc[c4 * 4 + 3] += sv * wv.w;
            }
        }
        __syncthreads();
    }

    float m = -1e30f;
    #pragma unroll
    for (int c = 0; c < 32; c++) {
        acc[c] += bd[q * 32 + c];
        m = fmaxf(m, acc[c]);
    }
    m = fmaxf(m, __shfl_xor_sync(0xFFFFFFFFu, m, 1));
    m = fmaxf(m, __shfl_xor_sync(0xFFFFFFFFu, m, 2));

    float sum = 0.f;
    #pragma unroll
    for (int c = 0; c < 32; c++) {
        acc[c] = expf(acc[c] - m);
        sum += acc[c];
    }
    sum += __shfl_xor_sync(0xFFFFFFFFu, sum, 1);
    sum += __shfl_xor_sync(0xFFFFFFFFu, sum, 2);
    float inv = 1.0f / sum;

    float* orow = out + (size_t)(row0 + r) * VOC + q * 32;
    #pragma unroll
    for (int c4 = 0; c4 < 8; c4++) {
        float4 v;
        v.x = acc[c4 * 4 + 0] * inv;
        v.y = acc[c4 * 4 + 1] * inv;
        v.z = acc[c4 * 4 + 2] * inv;
        v.w = acc[c4 * 4 + 3] * inv;
        reinterpret_cast<float4*>(orow)[c4] = v;
    }
}

// ---------------- launcher ----------------
extern "C" void kernel_launch(void* const* d_in, const int* in_sizes, int n_in,
                              void* d_out, int out_size) {
    (void)in_sizes; (void)n_in; (void)out_size;
    const int*   tokens = (const int*)  d_in[0];
    const float* emb    = (const float*)d_in[1];
    const float* W      = (const float*)d_in[2];
    const float* U      = (const float*)d_in[3];
    const float* b      = (const float*)d_in[4];
    const float* Wd     = (const float*)d_in[5];
    const float* bd     = (const float*)d_in[6];
    float* out = (float*)d_out;

    cudaFuncSetAttribute(lstm_persist, cudaFuncAttributeMaxDynamicSharedMemorySize,
                         SMEM_TOTAL);

    prep_embW<<<128, 256>>>(emb, W, b);
    prep_U<<<dim3(128, 32), 256>>>(U);
    init_state<<<512, 256>>>();
    lstm_persist<<<NBLK, 512, SMEM_TOTAL>>>(tokens);
    decode_kernel<<<1024, 256>>>(Wd, bd, out);
}

// round 11
// speedup vs baseline: 1.0832x; 1.0832x over previous
#include <cuda_runtime.h>
#include <cuda_fp16.h>
#include <cstdint>
#include <cstddef>

#define TSEQ 512
#define BATCH 128
#define HDIM 1024
#define NZ 4096
#define VOC 128
#define EDIM 256
#define NBLK 128

// ---------------- static device buffers ----------------
__device__ half  d_U16[(size_t)NZ * HDIM];            // U^T fp16 [n][k], 8 MB
__device__ float d_embW[VOC * NZ];                    // emb@W + b  [v][n], 2 MB
__device__ half  d_A16[2][BATCH * HDIM];              // ping-pong h (fp16)
__device__ float d_S[(size_t)BATCH * TSEQ * HDIM];    // fp32 states, 256 MB
__device__ unsigned g_cnt;                            // grid barrier state
__device__ unsigned g_gen;

// ---------------- PTX helpers ----------------
__device__ __forceinline__ unsigned smaddr(const void* p) {
    return (unsigned)__cvta_generic_to_shared(p);
}
__device__ __forceinline__ void cpa16(void* dst, const void* src) {
    asm volatile("cp.async.cg.shared.global [%0], [%1], 16;\n"
                 :: "r"(smaddr(dst)), "l"(src));
}
__device__ __forceinline__ void ldsm_x4(unsigned* r, const void* p) {
    unsigned a = smaddr(p);
    asm volatile("ldmatrix.sync.aligned.m8n8.x4.shared.b16 {%0,%1,%2,%3}, [%4];\n"
                 : "=r"(r[0]), "=r"(r[1]), "=r"(r[2]), "=r"(r[3]) : "r"(a));
}
__device__ __forceinline__ void ldsm_x2(unsigned* r, const void* p) {
    unsigned a = smaddr(p);
    asm volatile("ldmatrix.sync.aligned.m8n8.x2.shared.b16 {%0,%1}, [%2];\n"
                 : "=r"(r[0]), "=r"(r[1]) : "r"(a));
}
__device__ __forceinline__ void mma16816(float* d, const unsigned* a, const unsigned* b) {
    asm volatile("mma.sync.aligned.m16n8k16.row.col.f32.f16.f16.f32 "
                 "{%0,%1,%2,%3},{%4,%5,%6,%7},{%8,%9},{%0,%1,%2,%3};\n"
                 : "+f"(d[0]), "+f"(d[1]), "+f"(d[2]), "+f"(d[3])
                 : "r"(a[0]), "r"(a[1]), "r"(a[2]), "r"(a[3]),
                   "r"(b[0]), "r"(b[1]));
}
// ---- fast activations: single-instruction MUFU.TANH ----
__device__ __forceinline__ float ftanh(float x) {
    float r; asm("tanh.approx.f32 %0, %1;" : "=f"(r) : "f"(x)); return r;
}
__device__ __forceinline__ float fsig(float x) {
    float r; asm("tanh.approx.f32 %0, %1;" : "=f"(r) : "f"(0.5f * x));
    return fmaf(0.5f, r, 0.5f);
}

// ---------------- prep: embW = emb @ W + b   (128 x 4096, K=256) ----------------
__global__ void __launch_bounds__(256) prep_embW(const float* __restrict__ emb,
                                                 const float* __restrict__ W,
                                                 const float* __restrict__ bias) {
    __shared__ float Ws[EDIM][32];
    const int n0 = blockIdx.x * 32;
    for (int i = threadIdx.x; i < EDIM * 32; i += 256) {
        int e = i >> 5, c = i & 31;
        Ws[e][c] = W[(size_t)e * NZ + n0 + c];
    }
    __syncthreads();
    const int c = threadIdx.x & 31;
    for (int v = threadIdx.x >> 5; v < VOC; v += 8) {
        float a = bias[n0 + c];
        const float* er = emb + v * EDIM;
        #pragma unroll 8
        for (int e = 0; e < EDIM; e++) a += er[e] * Ws[e][c];
        d_embW[v * NZ + n0 + c] = a;
    }
}

// ---------------- prep: U fp32 [k][n] -> d_U16 fp16 [n][k] ----------------
__global__ void __launch_bounds__(256) prep_U(const float* __restrict__ U) {
    __shared__ float tile[32][33];
    const int n0 = blockIdx.x * 32;
    const int k0 = blockIdx.y * 32;
    const int tx = threadIdx.x & 31, ty = threadIdx.x >> 5;
    #pragma unroll
    for (int i = 0; i < 4; i++) {
        int r = ty + i * 8;
        tile[r][tx] = U[(size_t)(k0 + r) * NZ + n0 + tx];
    }
    __syncthreads();
    #pragma unroll
    for (int i = 0; i < 4; i++) {
        int r = ty + i * 8;
        d_U16[(size_t)(n0 + r) * HDIM + k0 + tx] = __float2half_rn(tile[tx][r]);
    }
}

__global__ void init_state() {
    int i = blockIdx.x * blockDim.x + threadIdx.x;
    if (i < BATCH * HDIM) d_A16[0][i] = __float2half_rn(0.f);
}

// ---------------- persistent LSTM ----------------
// Block bn owns h-cols [8bn,8bn+8) => z-cols {g*1024 + 8bn + j}.
// 16 warps = 4 M-groups (wm: 32 rows) x 4 K-slices (kw: 256 k).
// Warp-private 2-stage A rings, no mainloop barriers. c,h in registers.
// K-partials in smem layout [r][c][kw] -> LDS.128 reduce.
#define KC 64
#define B_ROWH 1032                             // 1024 + 8 pad halfs
#define B_H    (32 * B_ROWH)                    // 33024 halfs = 66048 B
#define A_STG_H (32 * 72)                       // 2304 halfs = 4608 B per stage
#define SMEM_TOTAL ((B_H + 16 * 2 * A_STG_H) * 2)   // 66048 + 147456 = 213504 B

__global__ void __launch_bounds__(512) lstm_persist(const int* __restrict__ tokens) {
    extern __shared__ __align__(16) half smh[];
    half*  Bs   = smh;                                   // B[32][1032]
    float* part = reinterpret_cast<float*>(smh + B_H);   // [128][33][4] = 67584 B

    const int tid  = threadIdx.x;
    const int bn   = blockIdx.x;
    const int lane = tid & 31, wid = tid >> 5;
    const int wm   = wid & 3;      // M-group: rows [wm*32, wm*32+32)
    const int kw   = wid >> 2;     // K-slice: k in [kw*256, kw*256+256)

    half* Aw = smh + B_H + wid * (2 * A_STG_H);          // private 2-stage ring

    unsigned gen = 0;
    if (tid == 0) gen = *(volatile unsigned*)&g_gen;

    // ---- c/h state in registers: thread owns (bb = e>>3, col = bn*8 + (e&7))
    // for e = tid and e = tid+512; mapping fixed for all 512 steps.
    float c_reg[2] = {0.f, 0.f};
    float h_reg[2] = {0.f, 0.f};

    // ---- B preload ONCE: 32 cols x 1024 k ----
    #pragma unroll
    for (int w = 0; w < 8; w++) {
        int i = tid + w * 512;                 // 0..4095
        int ci = i >> 7, seg = i & 127;
        int gcol = (ci >> 3) * HDIM + bn * 8 + (ci & 7);
        cpa16(Bs + ci * B_ROWH + seg * 8, d_U16 + (size_t)gcol * HDIM + seg * 8);
    }
    asm volatile("cp.async.commit_group;\ncp.async.wait_group 0;\n");
    __syncthreads();

    const int aRowL = (lane & 7) + ((lane >> 3) & 1) * 8;
    const int aCol  = ((lane >> 4) & 1) * 8;
    const int bKsel = ((lane >> 3) & 1) * 8;

    for (int t = 0; t < TSEQ; t++) {
        const int rb = t & 1, wb = rb ^ 1;
        const half* __restrict__ Asrc = d_A16[rb];

        // warp-private A loader: 32 rows x 64 k = 256 x 16B, 8 cpa16/lane
        auto load_A = [&](int ch) {
            half* st = Aw + (ch & 1) * A_STG_H;
            const int k0 = kw * 256 + ch * KC;
            #pragma unroll
            for (int w = 0; w < 8; w++) {
                int i = lane + w * 32;                    // 0..255
                int row = i >> 3, seg = i & 7;
                cpa16(st + row * 72 + seg * 8,
                      Asrc + (size_t)(wm * 32 + row) * HDIM + k0 + seg * 8);
            }
            asm volatile("cp.async.commit_group;\n");
        };
        load_A(0); load_A(1);

        float acc[2][4][4];
        #pragma unroll
        for (int i = 0; i < 2; i++)
            #pragma unroll
            for (int j = 0; j < 4; j++)
                #pragma unroll
                for (int e = 0; e < 4; e++) acc[i][j][e] = 0.f;

        for (int ch = 0; ch < 4; ch++) {
            asm volatile("cp.async.wait_group 1;\n");     // chunk ch resident (private)

            const half* st = Aw + (ch & 1) * A_STG_H;
            const int kOffB = kw * 256 + ch * KC + bKsel;
            #pragma unroll
            for (int ks = 0; ks < 4; ks++) {
                unsigned af0[4], af1[4], bf[4][2];
                ldsm_x4(af0, st + (aRowL     ) * 72 + aCol + ks * 16);
                ldsm_x4(af1, st + (aRowL + 16) * 72 + aCol + ks * 16);
                #pragma unroll
                for (int nt = 0; nt < 4; nt++)
                    ldsm_x2(bf[nt], Bs + (nt * 8 + (lane & 7)) * B_ROWH
                                       + kOffB + ks * 16);
                #pragma unroll
                for (int nt = 0; nt < 4; nt++) {
                    mma16816(acc[0][nt], af0, bf[nt]);
                    mma16816(acc[1][nt], af1, bf[nt]);
                }
            }

            if (ch < 2) load_A(ch + 2);                   // slot freed: MMAs issued
            else asm volatile("cp.async.commit_group;\n");
        }
        asm volatile("cp.async.wait_group 0;\n");
        __syncthreads();                                   // all warps done with A/B reads

        // ---- store K-partials: layout part[r][c][kw] ----
        #pragma unroll
        for (int mt = 0; mt < 2; mt++)
            #pragma unroll
            for (int nt = 0; nt < 4; nt++)
                #pragma unroll
                for (int e = 0; e < 4; e++) {
                    int r = wm * 32 + mt * 16 + (lane >> 2) + (e >> 1) * 8;
                    int c = nt * 8 + (lane & 3) * 2 + (e & 1);
                    part[(r * 33 + c) * 4 + kw] = acc[mt][nt][e];
                }
        __syncthreads();

        // ---- reduce (LDS.128) + gate + state update: 2 elements/thread ----
        const float4* p4 = reinterpret_cast<const float4*>(part);
        #pragma unroll
        for (int rep = 0; rep < 2; rep++) {
            const int e   = tid + rep * 512;
            const int bb  = e >> 3, j = e & 7;
            const int col = bn * 8 + j;
            const int tok = tokens[bb * TSEQ + t];
            const float* ew = d_embW + (size_t)tok * NZ + col;

            float4 vi = p4[bb * 33 + j];
            float4 vf = p4[bb * 33 + 8 + j];
            float4 vg = p4[bb * 33 + 16 + j];
            float4 vo = p4[bb * 33 + 24 + j];

            float zi = ((vi.x + vi.y) + (vi.z + vi.w)) + ew[0];
            float zf = ((vf.x + vf.y) + (vf.z + vf.w)) + ew[HDIM];
            float zg = ((vg.x + vg.y) + (vg.z + vg.w)) + ew[2 * HDIM];
            float zo = ((vo.x + vo.y) + (vo.z + vo.w)) + ew[3 * HDIM];

            float ig = fsig(zi);
            float fg = fsig(zf);
            float gg = ftanh(zg);
            float og = fsig(zo);

            float cp = c_reg[rep];
            float cn = fg * cp + ig * gg;
            float hn = og * ftanh(cn);

            bool msk = (tok != 0);
            float ho = msk ? hn : h_reg[rep];
            float co = msk ? cn : cp;

            c_reg[rep] = co;
            h_reg[rep] = ho;
            d_S[((size_t)bb * TSEQ + t) * HDIM + col] = ho;
            d_A16[wb][bb * HDIM + col] = __float2half_rn(ho);
        }

        // ---- grid barrier: h(t) published to all blocks ----
        __threadfence();
        __syncthreads();
        if (tid == 0) {
            unsigned arr = atomicAdd(&g_cnt, 1);
            if (arr == NBLK - 1) {
                g_cnt = 0;
                __threadfence();
                atomicExch(&g_gen, gen + 1);
            } else {
                while (*(volatile unsigned*)&g_gen != gen + 1) { }
            }
            __threadfence();
        }
        __syncthreads();
        gen++;
    }
}

// ---------------- decode + softmax ----------------
__global__ void __launch_bounds__(256) decode_kernel(const float* __restrict__ Wd,
                                                     const float* __restrict__ bd,
                                                     float* __restrict__ out) {
    __shared__ float s[64][33];
    __shared__ float w[32][128];
    const int row0 = blockIdx.x * 64;
    const int tid  = threadIdx.x;
    const int r    = tid >> 2;
    const int q    = tid & 3;

    float acc[32];
    #pragma unroll
    for (int i = 0; i < 32; i++) acc[i] = 0.f;

    for (int kt = 0; kt < 32; kt++) {
        for (int i = tid; i < 64 * 32; i += 256) {
            int rr = i >> 5, kk = i & 31;
            s[rr][kk] = d_S[(size_t)(row0 + rr) * HDIM + kt * 32 + kk];
        }
        for (int i = tid; i < 32 * 128; i += 256) {
            int kk = i >> 7, cc = i & 127;
            w[kk][cc] = Wd[(size_t)(kt * 32 + kk) * VOC + cc];
        }
        __syncthreads();

        #pragma unroll 4
        for (int kk = 0; kk < 32; kk++) {
            float sv = s[r][kk];
            const float4* wrow = reinterpret_cast<const float4*>(&w[kk][q * 32]);
            #pragma unroll
            for (int c4 = 0; c4 < 8; c4++) {
                float4 wv = wrow[c4];
                acc[c4 * 4 + 0] += sv * wv.x;
                acc[c4 * 4 + 1] += sv * wv.y;
                acc[c4 * 4 + 2] += sv * wv.z;
                acc[c4 * 4 + 3] += sv * wv.w;
            }
        }
        __syncthreads();
    }

    float m = -1e30f;
    #pragma unroll
    for (int c = 0; c < 32; c++) {
        acc[c] += bd[q * 32 + c];
        m = fmaxf(m, acc[c]);
    }
    m = fmaxf(m, __shfl_xor_sync(0xFFFFFFFFu, m, 1));
    m = fmaxf(m, __shfl_xor_sync(0xFFFFFFFFu, m, 2));

    float sum = 0.f;
    #pragma unroll
    for (int c = 0; c < 32; c++) {
        acc[c] = expf(acc[c] - m);
        sum += acc[c];
    }
    sum += __shfl_xor_sync(0xFFFFFFFFu, sum, 1);
    sum += __shfl_xor_sync(0xFFFFFFFFu, sum, 2);
    float inv = 1.0f / sum;

    float* orow = out + (size_t)(row0 + r) * VOC + q * 32;
    #pragma unroll
    for (int c4 = 0; c4 < 8; c4++) {
        float4 v;
        v.x = acc[c4 * 4 + 0] * inv;
        v.y = acc[c4 * 4 + 1] * inv;
        v.z = acc[c4 * 4 + 2] * inv;
        v.w = acc[c4 * 4 + 3] * inv;
        reinterpret_cast<float4*>(orow)[c4] = v;
    }
}

// ---------------- launcher ----------------
extern "C" void kernel_launch(void* const* d_in, const int* in_sizes, int n_in,
                              void* d_out, int out_size) {
    (void)in_sizes; (void)n_in; (void)out_size;
    const int*   tokens = (const int*)  d_in[0];
    const float* emb    = (const float*)d_in[1];
    const float* W      = (const float*)d_in[2];
    const float* U      = (const float*)d_in[3];
    const float* b      = (const float*)d_in[4];
    const float* Wd     = (const float*)d_in[5];
    const float* bd     = (const float*)d_in[6];
    float* out = (float*)d_out;

    cudaFuncSetAttribute(lstm_persist, cudaFuncAttributeMaxDynamicSharedMemorySize,
                         SMEM_TOTAL);

    prep_embW<<<128, 256>>>(emb, W, b);
    prep_U<<<dim3(128, 32), 256>>>(U);
    init_state<<<512, 256>>>();
    lstm_persist<<<NBLK, 512, SMEM_TOTAL>>>(tokens);
    decode_kernel<<<1024, 256>>>(Wd, bd, out);
}

// round 12
// speedup vs baseline: 1.1234x; 1.0371x over previous
#include <cuda_runtime.h>
#include <cuda_fp16.h>
#include <cstdint>
#include <cstddef>

#define TSEQ 512
#define BATCH 128
#define HDIM 1024
#define NZ 4096
#define VOC 128
#define EDIM 256
#define NBLK 128

// ---------------- static device buffers ----------------
__device__ half  d_U16[(size_t)NZ * HDIM];            // U^T fp16 [n][k], 8 MB
__device__ float d_embW[VOC * NZ];                    // emb@W + b  [v][n], 2 MB
__device__ half  d_A16[2][BATCH * HDIM];              // ping-pong h (fp16)
__device__ float d_S[(size_t)BATCH * TSEQ * HDIM];    // fp32 states, 256 MB
__device__ unsigned g_qcnt[4];                        // per-k-quarter release counters

// ---------------- PTX helpers ----------------
__device__ __forceinline__ unsigned smaddr(const void* p) {
    return (unsigned)__cvta_generic_to_shared(p);
}
__device__ __forceinline__ void cpa16(void* dst, const void* src) {
    asm volatile("cp.async.cg.shared.global [%0], [%1], 16;\n"
                 :: "r"(smaddr(dst)), "l"(src));
}
__device__ __forceinline__ void ldsm_x4(unsigned* r, const void* p) {
    unsigned a = smaddr(p);
    asm volatile("ldmatrix.sync.aligned.m8n8.x4.shared.b16 {%0,%1,%2,%3}, [%4];\n"
                 : "=r"(r[0]), "=r"(r[1]), "=r"(r[2]), "=r"(r[3]) : "r"(a));
}
__device__ __forceinline__ void ldsm_x2(unsigned* r, const void* p) {
    unsigned a = smaddr(p);
    asm volatile("ldmatrix.sync.aligned.m8n8.x2.shared.b16 {%0,%1}, [%2];\n"
                 : "=r"(r[0]), "=r"(r[1]) : "r"(a));
}
__device__ __forceinline__ void mma16816(float* d, const unsigned* a, const unsigned* b) {
    asm volatile("mma.sync.aligned.m16n8k16.row.col.f32.f16.f16.f32 "
                 "{%0,%1,%2,%3},{%4,%5,%6,%7},{%8,%9},{%0,%1,%2,%3};\n"
                 : "+f"(d[0]), "+f"(d[1]), "+f"(d[2]), "+f"(d[3])
                 : "r"(a[0]), "r"(a[1]), "r"(a[2]), "r"(a[3]),
                   "r"(b[0]), "r"(b[1]));
}
// ---- fast activations: single-instruction MUFU.TANH ----
__device__ __forceinline__ float ftanh(float x) {
    float r; asm("tanh.approx.f32 %0, %1;" : "=f"(r) : "f"(x)); return r;
}
__device__ __forceinline__ float fsig(float x) {
    float r; asm("tanh.approx.f32 %0, %1;" : "=f"(r) : "f"(0.5f * x));
    return fmaf(0.5f, r, 0.5f);
}

// ---------------- prep: embW = emb @ W + b   (128 x 4096, K=256) ----------------
__global__ void __launch_bounds__(256) prep_embW(const float* __restrict__ emb,
                                                 const float* __restrict__ W,
                                                 const float* __restrict__ bias) {
    __shared__ float Ws[EDIM][32];
    const int n0 = blockIdx.x * 32;
    for (int i = threadIdx.x; i < EDIM * 32; i += 256) {
        int e = i >> 5, c = i & 31;
        Ws[e][c] = W[(size_t)e * NZ + n0 + c];
    }
    __syncthreads();
    const int c = threadIdx.x & 31;
    for (int v = threadIdx.x >> 5; v < VOC; v += 8) {
        float a = bias[n0 + c];
        const float* er = emb + v * EDIM;
        #pragma unroll 8
        for (int e = 0; e < EDIM; e++) a += er[e] * Ws[e][c];
        d_embW[v * NZ + n0 + c] = a;
    }
}

// ---------------- prep: U fp32 [k][n] -> d_U16 fp16 [n][k] ----------------
__global__ void __launch_bounds__(256) prep_U(const float* __restrict__ U) {
    __shared__ float tile[32][33];
    const int n0 = blockIdx.x * 32;
    const int k0 = blockIdx.y * 32;
    const int tx = threadIdx.x & 31, ty = threadIdx.x >> 5;
    #pragma unroll
    for (int i = 0; i < 4; i++) {
        int r = ty + i * 8;
        tile[r][tx] = U[(size_t)(k0 + r) * NZ + n0 + tx];
    }
    __syncthreads();
    #pragma unroll
    for (int i = 0; i < 4; i++) {
        int r = ty + i * 8;
        d_U16[(size_t)(n0 + r) * HDIM + k0 + tx] = __float2half_rn(tile[tx][r]);
    }
}

__global__ void init_state() {
    int i = blockIdx.x * blockDim.x + threadIdx.x;
    if (i < BATCH * HDIM) d_A16[0][i] = __float2half_rn(0.f);
    if (blockIdx.x == 0 && threadIdx.x < 4) g_qcnt[threadIdx.x] = 0;
}

// ---------------- persistent LSTM ----------------
// Block bn owns h-cols [8bn,8bn+8) => z-cols {g*1024 + 8bn + j}.
// 16 warps = 4 M-groups (wm) x 4 K-slices (kw). Warp-private 2-stage A rings.
// Cross-block sync: per-k-quarter release counters (no full grid barrier).
#define KC 64
#define B_ROWH 1032                             // 1024 + 8 pad halfs
#define B_H    (32 * B_ROWH)                    // 33024 halfs = 66048 B
#define A_STG_H (32 * 72)                       // 2304 halfs = 4608 B per stage
#define SMEM_TOTAL ((B_H + 16 * 2 * A_STG_H) * 2)   // 66048 + 147456 = 213504 B

__global__ void __launch_bounds__(512) lstm_persist(const int* __restrict__ tokens) {
    extern __shared__ __align__(16) half smh[];
    half*  Bs   = smh;                                   // B[32][1032]
    float* part = reinterpret_cast<float*>(smh + B_H);   // [128][33][4] = 67584 B

    const int tid  = threadIdx.x;
    const int bn   = blockIdx.x;
    const int lane = tid & 31, wid = tid >> 5;
    const int wm   = wid & 3;      // M-group: rows [wm*32, wm*32+32)
    const int kw   = wid >> 2;     // K-slice: k in [kw*256, kw*256+256)
    const int myq  = bn >> 5;      // quarter this block produces into

    half* Aw = smh + B_H + wid * (2 * A_STG_H);          // private 2-stage ring

    // ---- c/h state in registers; thread owns (bb0, col) and (bb1, col) ----
    const int bb0 = tid >> 3, bb1 = bb0 + 64;
    const int col = bn * 8 + (tid & 7);
    float c_reg[2] = {0.f, 0.f};
    float h_reg[2] = {0.f, 0.f};

    // ---- B preload ONCE: 32 cols x 1024 k ----
    #pragma unroll
    for (int w = 0; w < 8; w++) {
        int i = tid + w * 512;                 // 0..4095
        int ci = i >> 7, seg = i & 127;
        int gcol = (ci >> 3) * HDIM + bn * 8 + (ci & 7);
        cpa16(Bs + ci * B_ROWH + seg * 8, d_U16 + (size_t)gcol * HDIM + seg * 8);
    }
    asm volatile("cp.async.commit_group;\ncp.async.wait_group 0;\n");
    __syncthreads();

    const int aRowL = (lane & 7) + ((lane >> 3) & 1) * 8;
    const int aCol  = ((lane >> 4) & 1) * 8;
    const int bKsel = ((lane >> 3) & 1) * 8;

    for (int t = 0; t < TSEQ; t++) {
        const int rb = t & 1, wb = rb ^ 1;
        const half* __restrict__ Asrc = d_A16[rb];

        // ---- prefetch gate inputs (independent of h) ----
        const int tk0 = tokens[bb0 * TSEQ + t];
        const int tk1 = tokens[bb1 * TSEQ + t];
        const float* e0 = d_embW + (size_t)tk0 * NZ + col;
        const float* e1 = d_embW + (size_t)tk1 * NZ + col;
        float ew0i = e0[0], ew0f = e0[HDIM], ew0g = e0[2 * HDIM], ew0o = e0[3 * HDIM];
        float ew1i = e1[0], ew1f = e1[HDIM], ew1g = e1[2 * HDIM], ew1o = e1[3 * HDIM];

        // ---- acquire own k-quarter: h(t-1) of cols [kw*256, kw*256+256) ready ----
        if (lane == 0) {
            const unsigned target = 32u * (unsigned)t;
            unsigned v;
            asm volatile("ld.acquire.gpu.global.u32 %0, [%1];"
                         : "=r"(v) : "l"(&g_qcnt[kw]) : "memory");
            while (v < target) {
                __nanosleep(64);
                asm volatile("ld.acquire.gpu.global.u32 %0, [%1];"
                             : "=r"(v) : "l"(&g_qcnt[kw]) : "memory");
            }
        }
        __syncwarp();

        // warp-private A loader: 32 rows x 64 k = 256 x 16B, 8 cpa16/lane
        auto load_A = [&](int ch) {
            half* st = Aw + (ch & 1) * A_STG_H;
            const int k0 = kw * 256 + ch * KC;
            #pragma unroll
            for (int w = 0; w < 8; w++) {
                int i = lane + w * 32;                    // 0..255
                int row = i >> 3, seg = i & 7;
                cpa16(st + row * 72 + seg * 8,
                      Asrc + (size_t)(wm * 32 + row) * HDIM + k0 + seg * 8);
            }
            asm volatile("cp.async.commit_group;\n");
        };
        load_A(0); load_A(1);

        float acc[2][4][4];
        #pragma unroll
        for (int i = 0; i < 2; i++)
            #pragma unroll
            for (int j = 0; j < 4; j++)
                #pragma unroll
                for (int e = 0; e < 4; e++) acc[i][j][e] = 0.f;

        for (int ch = 0; ch < 4; ch++) {
            asm volatile("cp.async.wait_group 1;\n");     // chunk ch resident (private)

            const half* st = Aw + (ch & 1) * A_STG_H;
            const int kOffB = kw * 256 + ch * KC + bKsel;
            #pragma unroll
            for (int ks = 0; ks < 4; ks++) {
                unsigned af0[4], af1[4], bf[4][2];
                ldsm_x4(af0, st + (aRowL     ) * 72 + aCol + ks * 16);
                ldsm_x4(af1, st + (aRowL + 16) * 72 + aCol + ks * 16);
                #pragma unroll
                for (int nt = 0; nt < 4; nt++)
                    ldsm_x2(bf[nt], Bs + (nt * 8 + (lane & 7)) * B_ROWH
                                       + kOffB + ks * 16);
                #pragma unroll
                for (int nt = 0; nt < 4; nt++) {
                    mma16816(acc[0][nt], af0, bf[nt]);
                    mma16816(acc[1][nt], af1, bf[nt]);
                }
            }

            if (ch < 2) load_A(ch + 2);                   // slot freed: MMAs issued
            else asm volatile("cp.async.commit_group;\n");
        }
        asm volatile("cp.async.wait_group 0;\n");
        __syncthreads();                                   // S1: all GEMM reads done

        // ---- store K-partials: layout part[r][c][kw] ----
        #pragma unroll
        for (int mt = 0; mt < 2; mt++)
            #pragma unroll
            for (int nt = 0; nt < 4; nt++)
                #pragma unroll
                for (int e = 0; e < 4; e++) {
                    int r = wm * 32 + mt * 16 + (lane >> 2) + (e >> 1) * 8;
                    int c = nt * 8 + (lane & 3) * 2 + (e & 1);
                    part[(r * 33 + c) * 4 + kw] = acc[mt][nt][e];
                }
        __syncthreads();                                   // S2: partials published

        // ---- reduce (LDS.128) + gate + state update: 2 elements/thread ----
        const float4* p4 = reinterpret_cast<const float4*>(part);
        #pragma unroll
        for (int rep = 0; rep < 2; rep++) {
            const int bb = rep ? bb1 : bb0;
            const int tk = rep ? tk1 : tk0;

            float4 vi = p4[bb * 33 + (tid & 7)];
            float4 vf = p4[bb * 33 + 8 + (tid & 7)];
            float4 vg = p4[bb * 33 + 16 + (tid & 7)];
            float4 vo = p4[bb * 33 + 24 + (tid & 7)];

            float zi = ((vi.x + vi.y) + (vi.z + vi.w)) + (rep ? ew1i : ew0i);
            float zf = ((vf.x + vf.y) + (vf.z + vf.w)) + (rep ? ew1f : ew0f);
            float zg = ((vg.x + vg.y) + (vg.z + vg.w)) + (rep ? ew1g : ew0g);
            float zo = ((vo.x + vo.y) + (vo.z + vo.w)) + (rep ? ew1o : ew0o);

            float ig = fsig(zi);
            float fg = fsig(zf);
            float gg = ftanh(zg);
            float og = fsig(zo);

            float cp = c_reg[rep];
            float cn = fg * cp + ig * gg;
            float hn = og * ftanh(cn);

            bool msk = (tk != 0);
            float ho = msk ? hn : h_reg[rep];
            float co = msk ? cn : cp;

            c_reg[rep] = co;
            h_reg[rep] = ho;
            d_S[((size_t)bb * TSEQ + t) * HDIM + col] = ho;
            d_A16[wb][bb * HDIM + col] = __float2half_rn(ho);
        }

        // ---- release: h(t) of this block's quarter published ----
        __syncthreads();                                   // S3: all h stores done
        if (tid == 0) {
            asm volatile("red.release.gpu.global.add.u32 [%0], 1;"
                         :: "l"(&g_qcnt[myq]) : "memory");
        }
    }
}

// ---------------- decode + softmax ----------------
__global__ void __launch_bounds__(256) decode_kernel(const float* __restrict__ Wd,
                                                     const float* __restrict__ bd,
                                                     float* __restrict__ out) {
    __shared__ float s[64][33];
    __shared__ float w[32][128];
    const int row0 = blockIdx.x * 64;
    const int tid  = threadIdx.x;
    const int r    = tid >> 2;
    const int q    = tid & 3;

    float acc[32];
    #pragma unroll
    for (int i = 0; i < 32; i++) acc[i] = 0.f;

    for (int kt = 0; kt < 32; kt++) {
        for (int i = tid; i < 64 * 32; i += 256) {
            int rr = i >> 5, kk = i & 31;
            s[rr][kk] = d_S[(size_t)(row0 + rr) * HDIM + kt * 32 + kk];
        }
        for (int i = tid; i < 32 * 128; i += 256) {
            int kk = i >> 7, cc = i & 127;
            w[kk][cc] = Wd[(size_t)(kt * 32 + kk) * VOC + cc];
        }
        __syncthreads();

        #pragma unroll 4
        for (int kk = 0; kk < 32; kk++) {
            float sv = s[r][kk];
            const float4* wrow = reinterpret_cast<const float4*>(&w[kk][q * 32]);
            #pragma unroll
            for (int c4 = 0; c4 < 8; c4++) {
                float4 wv = wrow[c4];
                acc[c4 * 4 + 0] += sv * wv.x;
                acc[c4 * 4 + 1] += sv * wv.y;
                acc[c4 * 4 + 2] += sv * wv.z;
                acc[c4 * 4 + 3] += sv * wv.w;
            }
        }
        __syncthreads();
    }

    float m = -1e30f;
    #pragma unroll
    for (int c = 0; c < 32; c++) {
        acc[c] += bd[q * 32 + c];
        m = fmaxf(m, acc[c]);
    }
    m = fmaxf(m, __shfl_xor_sync(0xFFFFFFFFu, m, 1));
    m = fmaxf(m, __shfl_xor_sync(0xFFFFFFFFu, m, 2));

    float sum = 0.f;
    #pragma unroll
    for (int c = 0; c < 32; c++) {
        acc[c] = expf(acc[c] - m);
        sum += acc[c];
    }
    sum += __shfl_xor_sync(0xFFFFFFFFu, sum, 1);
    sum += __shfl_xor_sync(0xFFFFFFFFu, sum, 2);
    float inv = 1.0f / sum;

    float* orow = out + (size_t)(row0 + r) * VOC + q * 32;
    #pragma unroll
    for (int c4 = 0; c4 < 8; c4++) {
        float4 v;
        v.x = acc[c4 * 4 + 0] * inv;
        v.y = acc[c4 * 4 + 1] * inv;
        v.z = acc[c4 * 4 + 2] * inv;
        v.w = acc[c4 * 4 + 3] * inv;
        reinterpret_cast<float4*>(orow)[c4] = v;
    }
}

// ---------------- launcher ----------------
extern "C" void kernel_launch(void* const* d_in, const int* in_sizes, int n_in,
                              void* d_out, int out_size) {
    (void)in_sizes; (void)n_in; (void)out_size;
    const int*   tokens = (const int*)  d_in[0];
    const float* emb    = (const float*)d_in[1];
    const float* W      = (const float*)d_in[2];
    const float* U      = (const float*)d_in[3];
    const float* b      = (const float*)d_in[4];
    const float* Wd     = (const float*)d_in[5];
    const float* bd     = (const float*)d_in[6];
    float* out = (float*)d_out;

    cudaFuncSetAttribute(lstm_persist, cudaFuncAttributeMaxDynamicSharedMemorySize,
                         SMEM_TOTAL);

    prep_embW<<<128, 256>>>(emb, W, b);
    prep_U<<<dim3(128, 32), 256>>>(U);
    init_state<<<512, 256>>>();
    lstm_persist<<<NBLK, 512, SMEM_TOTAL>>>(tokens);
    decode_kernel<<<1024, 256>>>(Wd, bd, out);
}